// round 5
// baseline (speedup 1.0000x reference)
#include <cuda_runtime.h>
#include <cuda_bf16.h>

// Inverse db1 DWT (Haar), grouped transposed conv 2x2 stride 2 — no overlap.
// x: (16, 128, 128, 128) f32; inv_filters: (2,2,2) f32
// out: (16, 64, 256, 256) f32
//
// out[b,g,2h+i,2w+j] = x[b,2g,h,w]*f0[i,j] + x[b,2g+1,h,w]*f1[i,j]
//
// One thread: 4 input pixels along w (float4 from lo chan + float4 from hi
// chan), writes 2 rows x 2 float4 of the 2x8 output patch. Streaming cache
// hints (no reuse anywhere). All accesses fully coalesced:
//   warp loads 512 B contiguous per channel; stores 1024 B contiguous per row.

static constexpr int B  = 16;
static constexpr int G  = 64;   // C/2 groups
static constexpr int H  = 128;
static constexpr int W  = 128;
static constexpr int W4 = W / 4;             // 32 quads per row
static constexpr long long TOTAL = (long long)B * G * H * W4;  // 4,194,304 threads

__global__ __launch_bounds__(256)
void iwt_kernel(const float4* __restrict__ x,
                const float*  __restrict__ f,
                float4* __restrict__ out)
{
    int idx = blockIdx.x * blockDim.x + threadIdx.x;   // < 2^22
    int w4 = idx & (W4 - 1);           // 0..31
    int h  = (idx >> 5) & (H - 1);     // 0..127
    int bg = idx >> 12;                // b*G + g, 0..1023

    // input (in float4 units): plane = H*W/4 = 4096 per channel
    int lo_off = (2 * bg) * (H * W / 4) + h * (W / 4) + w4;
    float4 lo = __ldcs(x + lo_off);
    float4 hi = __ldcs(x + lo_off + H * W / 4);

    // filters: f[0..3] = f0 row-major, f[4..7] = f1 row-major
    float f00 = __ldg(f + 0), f01 = __ldg(f + 1);
    float f02 = __ldg(f + 2), f03 = __ldg(f + 3);
    float g00 = __ldg(f + 4), g01 = __ldg(f + 5);
    float g02 = __ldg(f + 6), g03 = __ldg(f + 7);

    // output (in float4 units): plane per (b,g) = 256*256/4 = 16384
    // row 2h starts at bg*16384 + 2h*64; this thread covers float4s [2*w4, 2*w4+1]
    int o_off = bg * (2 * H * 2 * W / 4) + (2 * h) * (2 * W / 4) + 2 * w4;

    float4 a0, a1, b0, b1;
    // row 2h (filter row 0): pixels 0,1 -> a0 ; pixels 2,3 -> a1
    a0.x = fmaf(hi.x, g00, lo.x * f00);
    a0.y = fmaf(hi.x, g01, lo.x * f01);
    a0.z = fmaf(hi.y, g00, lo.y * f00);
    a0.w = fmaf(hi.y, g01, lo.y * f01);
    a1.x = fmaf(hi.z, g00, lo.z * f00);
    a1.y = fmaf(hi.z, g01, lo.z * f01);
    a1.z = fmaf(hi.w, g00, lo.w * f00);
    a1.w = fmaf(hi.w, g01, lo.w * f01);
    // row 2h+1 (filter row 1)
    b0.x = fmaf(hi.x, g02, lo.x * f02);
    b0.y = fmaf(hi.x, g03, lo.x * f03);
    b0.z = fmaf(hi.y, g02, lo.y * f02);
    b0.w = fmaf(hi.y, g03, lo.y * f03);
    b1.x = fmaf(hi.z, g02, lo.z * f02);
    b1.y = fmaf(hi.z, g03, lo.z * f03);
    b1.z = fmaf(hi.w, g02, lo.w * f02);
    b1.w = fmaf(hi.w, g03, lo.w * f03);

    __stcs(out + o_off,                 a0);
    __stcs(out + o_off + 1,             a1);
    __stcs(out + o_off + 2 * W / 4,     b0);
    __stcs(out + o_off + 2 * W / 4 + 1, b1);
}

extern "C" void kernel_launch(void* const* d_in, const int* in_sizes, int n_in,
                              void* d_out, int out_size)
{
    const float4* x = (const float4*)d_in[0];
    const float*  f = (const float*)d_in[1];
    float4* out     = (float4*)d_out;

    const int threads = 256;
    const int blocks  = (int)(TOTAL / threads);   // 16384, exact
    iwt_kernel<<<blocks, threads>>>(x, f, out);
}

// round 9
// speedup vs baseline: 1.0655x; 1.0655x over previous
#include <cuda_runtime.h>
#include <cuda_bf16.h>

// Inverse db1 DWT (Haar), grouped transposed conv 2x2 stride 2 — no overlap.
// x: (16, 128, 128, 128) f32; inv_filters: (2,2,2) f32
// out: (16, 64, 256, 256) f32
//
// out[b,g,2h+i,2w+j] = x[b,2g,h,w]*f0[i,j] + x[b,2g+1,h,w]*f1[i,j]
//
// Dense-per-instruction layout (the R4 lesson): each thread handles TWO
// pixel-pairs at lane-distance 32 (w2 and w2+32). Every load is a float2 with
// warp stride == 8 B (256 B dense) and every store is a float4 with warp
// stride == 16 B (512 B dense). MLP=4 loads in flight per thread.

static constexpr int B   = 16;
static constexpr int G   = 64;    // C/2 groups
static constexpr int H   = 128;
static constexpr int W   = 128;
static constexpr int HALF = 32;   // half of W2=64 pixel-pairs per row
static constexpr long long TOTAL = (long long)B * G * H * HALF;  // 4,194,304

__global__ __launch_bounds__(256)
void iwt_kernel(const float2* __restrict__ x,
                const float*  __restrict__ f,
                float4* __restrict__ out)
{
    int idx = blockIdx.x * blockDim.x + threadIdx.x;   // < 2^22
    int w2 = idx & (HALF - 1);         // 0..31  (lane-aligned)
    int h  = (idx >> 5) & (H - 1);     // 0..127
    int bg = idx >> 12;                // b*G + g, 0..1023

    // input in float2 units: channel plane = H*W/2 = 8192
    int in_base = (2 * bg) * (H * W / 2) + h * (W / 2) + w2;
    float2 lo0 = __ldcs(x + in_base);
    float2 lo1 = __ldcs(x + in_base + HALF);
    float2 hi0 = __ldcs(x + in_base + H * W / 2);
    float2 hi1 = __ldcs(x + in_base + H * W / 2 + HALF);

    // filters: f[0..3] = f0 row-major, f[4..7] = f1 row-major
    float f00 = __ldg(f + 0), f01 = __ldg(f + 1);
    float f02 = __ldg(f + 2), f03 = __ldg(f + 3);
    float g00 = __ldg(f + 4), g01 = __ldg(f + 5);
    float g02 = __ldg(f + 6), g03 = __ldg(f + 7);

    // output in float4 units: plane per (b,g) = 256*256/4 = 16384
    // pixel-pair p -> output quad p in rows 2h and 2h+1
    int o_base = bg * (2 * H * 2 * W / 4) + (2 * h) * (2 * W / 4) + w2;
    int o_row  = 2 * W / 4;   // 64 quads per output row

    float4 r;
    // pair 0, row 2h
    r.x = fmaf(hi0.x, g00, lo0.x * f00);
    r.y = fmaf(hi0.x, g01, lo0.x * f01);
    r.z = fmaf(hi0.y, g00, lo0.y * f00);
    r.w = fmaf(hi0.y, g01, lo0.y * f01);
    __stcs(out + o_base, r);
    // pair 1, row 2h
    r.x = fmaf(hi1.x, g00, lo1.x * f00);
    r.y = fmaf(hi1.x, g01, lo1.x * f01);
    r.z = fmaf(hi1.y, g00, lo1.y * f00);
    r.w = fmaf(hi1.y, g01, lo1.y * f01);
    __stcs(out + o_base + HALF, r);
    // pair 0, row 2h+1
    r.x = fmaf(hi0.x, g02, lo0.x * f02);
    r.y = fmaf(hi0.x, g03, lo0.x * f03);
    r.z = fmaf(hi0.y, g02, lo0.y * f02);
    r.w = fmaf(hi0.y, g03, lo0.y * f03);
    __stcs(out + o_base + o_row, r);
    // pair 1, row 2h+1
    r.x = fmaf(hi1.x, g02, lo1.x * f02);
    r.y = fmaf(hi1.x, g03, lo1.x * f03);
    r.z = fmaf(hi1.y, g02, lo1.y * f02);
    r.w = fmaf(hi1.y, g03, lo1.y * f03);
    __stcs(out + o_base + o_row + HALF, r);
}

extern "C" void kernel_launch(void* const* d_in, const int* in_sizes, int n_in,
                              void* d_out, int out_size)
{
    const float2* x = (const float2*)d_in[0];
    const float*  f = (const float*)d_in[1];
    float4* out     = (float4*)d_out;

    const int threads = 256;
    const int blocks  = (int)(TOTAL / threads);   // 16384, exact
    iwt_kernel<<<blocks, threads>>>(x, f, out);
}